// round 2
// baseline (speedup 1.0000x reference)
#include <cuda_runtime.h>
#include <math.h>

// Problem constants
#define BATCH 16384
#define DIM   768
#define NEXP  124
#define NCLS  6
#define NEC   (NEXP * NCLS)   // 744

// Scratch (static device globals -- allocation-free at runtime)
__device__ float g_h[3 * BATCH * DIM];        // gelu(fc1) outputs for cls/we/ew
__device__ float g_cls_logits[BATCH * NEC];   // [B, 744]
__device__ float g_we_logits[BATCH * NEXP];   // [B, 124]
__device__ float g_ew_logits[BATCH * NEXP];   // [B, 124]

__device__ __forceinline__ float gelu_exact(float x) {
    return 0.5f * x * (1.0f + erff(x * 0.70710678118654752f));
}

// ---------------------------------------------------------------------------
// SGEMM: out[M,N] = act(A[M,K] @ W[K,N] + bias[N]),  M=16384, K=768 fixed.
// BM=BN=128, BK=8, 256 threads, 8x8 per thread with 4+64 column/row split
// (conflict-free LDS.128).
// ---------------------------------------------------------------------------
#define BM 128
#define BN 128
#define BK 8

__global__ __launch_bounds__(256, 2)
void sgemm_bias_act(const float* __restrict__ A,
                    const float* __restrict__ W,
                    const float* __restrict__ bias,
                    float* __restrict__ out,
                    int N, int applyGelu)
{
    const int K = DIM;
    __shared__ float As[BK][BM];
    __shared__ float Bs[BK][BN];

    const int tid = threadIdx.x;
    const int tx  = tid & 15;    // 0..15 -> cols
    const int ty  = tid >> 4;    // 0..15 -> rows
    const int m0  = blockIdx.y * BM;
    const int n0  = blockIdx.x * BN;

    // global load mapping
    const int aRow = tid >> 1;          // 0..127
    const int aCol = (tid & 1) * 4;     // 0 or 4
    const int bRow = tid >> 5;          // 0..7
    const int bCol = (tid & 31) * 4;    // 0..124

    float acc[8][8];
#pragma unroll
    for (int i = 0; i < 8; i++)
#pragma unroll
        for (int j = 0; j < 8; j++) acc[i][j] = 0.0f;

    for (int k0 = 0; k0 < K; k0 += BK) {
        // A tile (no M/K guards needed: M%128==0, K%8==0)
        float4 a4 = *(const float4*)(A + (m0 + aRow) * K + k0 + aCol);
        As[aCol + 0][aRow] = a4.x;
        As[aCol + 1][aRow] = a4.y;
        As[aCol + 2][aRow] = a4.z;
        As[aCol + 3][aRow] = a4.w;

        // B tile (guard N; N is a multiple of 4 and bc is a multiple of 4)
        int bc = n0 + bCol;
        float4 b4 = make_float4(0.f, 0.f, 0.f, 0.f);
        if (bc < N) b4 = *(const float4*)(W + (k0 + bRow) * N + bc);
        *(float4*)&Bs[bRow][bCol] = b4;

        __syncthreads();

#pragma unroll
        for (int kk = 0; kk < BK; kk++) {
            float ra[8], rb[8];
            *(float4*)&ra[0] = *(const float4*)&As[kk][ty * 4];
            *(float4*)&ra[4] = *(const float4*)&As[kk][64 + ty * 4];
            *(float4*)&rb[0] = *(const float4*)&Bs[kk][tx * 4];
            *(float4*)&rb[4] = *(const float4*)&Bs[kk][64 + tx * 4];
#pragma unroll
            for (int i = 0; i < 8; i++)
#pragma unroll
                for (int j = 0; j < 8; j++)
                    acc[i][j] = fmaf(ra[i], rb[j], acc[i][j]);
        }
        __syncthreads();
    }

    // epilogue: bias + optional gelu, guarded stores
#pragma unroll
    for (int i = 0; i < 8; i++) {
        int r = m0 + ((i < 4) ? (ty * 4 + i) : (64 + ty * 4 + i - 4));
#pragma unroll
        for (int jj = 0; jj < 2; jj++) {
            int c = n0 + ((jj == 0) ? (tx * 4) : (64 + tx * 4));
            if (c < N) {
                float4 bv = *(const float4*)(bias + c);
                float4 o;
                o.x = acc[i][jj * 4 + 0] + bv.x;
                o.y = acc[i][jj * 4 + 1] + bv.y;
                o.z = acc[i][jj * 4 + 2] + bv.z;
                o.w = acc[i][jj * 4 + 3] + bv.w;
                if (applyGelu) {
                    o.x = gelu_exact(o.x);
                    o.y = gelu_exact(o.y);
                    o.z = gelu_exact(o.z);
                    o.w = gelu_exact(o.w);
                }
                *(float4*)(out + (size_t)r * N + c) = o;
            }
        }
    }
}

// ---------------------------------------------------------------------------
// Epilogue: per row (one 128-thread block per row)
//   n = min(n_experts, E); threshold = n-th largest of which_expert
//   mask which < threshold -> -inf in expert-weight logits
//   softmax over experts, softmax over classes, weighted combine
// ---------------------------------------------------------------------------
__global__ __launch_bounds__(128)
void epilogue_kernel(const float* __restrict__ we_l,
                     const float* __restrict__ ew_l,
                     const float* __restrict__ cls_l,
                     const int*   __restrict__ n_experts,
                     float* __restrict__ out)
{
    const int row  = blockIdx.x;
    const int t    = threadIdx.x;
    const int lane = t & 31;
    const int warp = t >> 5;

    __shared__ float s_we[128];
    __shared__ float s_thr;
    __shared__ float s_red[4];
    __shared__ float s_part[4][NCLS];

    const float NEG_INF = -__int_as_float(0x7f800000);

    float v = (t < NEXP) ? we_l[row * NEXP + t] : NEG_INF;
    s_we[t] = v;
    __syncthreads();

    int n = n_experts[row];
    n = (n < NEXP) ? n : NEXP;

    if (t < NEXP) {
        int cgt = 0, ceq = 0;
#pragma unroll 4
        for (int j = 0; j < NEXP; j++) {
            float u = s_we[j];
            cgt += (u > v);
            ceq += (u == v);
        }
        if (cgt <= n - 1 && cgt + ceq > n - 1) s_thr = v;  // rank n-1 element
    }
    __syncthreads();
    float thr = s_thr;

    float ewv = NEG_INF;
    if (t < NEXP && v >= thr) ewv = ew_l[row * NEXP + t];

    // block max of ewv
    float m = ewv;
#pragma unroll
    for (int o = 16; o > 0; o >>= 1) m = fmaxf(m, __shfl_xor_sync(0xffffffffu, m, o));
    if (lane == 0) s_red[warp] = m;
    __syncthreads();
    m = fmaxf(fmaxf(s_red[0], s_red[1]), fmaxf(s_red[2], s_red[3]));
    __syncthreads();

    float e = expf(ewv - m);   // 0 for masked lanes (-inf - finite = -inf)

    // block sum of e
    float se = e;
#pragma unroll
    for (int o = 16; o > 0; o >>= 1) se += __shfl_xor_sync(0xffffffffu, se, o);
    if (lane == 0) s_red[warp] = se;
    __syncthreads();
    se = s_red[0] + s_red[1] + s_red[2] + s_red[3];

    // per-expert class softmax, weighted partials
    float part[NCLS];
#pragma unroll
    for (int c = 0; c < NCLS; c++) part[c] = 0.0f;
    if (t < NEXP) {
        float l[NCLS];
#pragma unroll
        for (int c = 0; c < NCLS; c++) l[c] = cls_l[row * NEC + t * NCLS + c];
        float mx = l[0];
#pragma unroll
        for (int c = 1; c < NCLS; c++) mx = fmaxf(mx, l[c]);
        float s = 0.0f;
#pragma unroll
        for (int c = 0; c < NCLS; c++) { l[c] = expf(l[c] - mx); s += l[c]; }
        float scale = e / s;
#pragma unroll
        for (int c = 0; c < NCLS; c++) part[c] = l[c] * scale;
    }

    // block reduce part[6]
#pragma unroll
    for (int c = 0; c < NCLS; c++) {
        float p = part[c];
#pragma unroll
        for (int o = 16; o > 0; o >>= 1) p += __shfl_xor_sync(0xffffffffu, p, o);
        part[c] = p;
    }
    if (lane == 0)
#pragma unroll
        for (int c = 0; c < NCLS; c++) s_part[warp][c] = part[c];
    __syncthreads();

    if (t < NCLS) {
        float tot = s_part[0][t] + s_part[1][t] + s_part[2][t] + s_part[3][t];
        // combined / weights.sum : softmax weights = e/se; sum of them = 1,
        // so result = (sum part)/se exactly matches reference numerics.
        out[row * NCLS + t] = tot / se;
    }
}

// ---------------------------------------------------------------------------
// Launch
// ---------------------------------------------------------------------------
extern "C" void kernel_launch(void* const* d_in, const int* in_sizes, int n_in,
                              void* d_out, int out_size)
{
    const float* x      = (const float*)d_in[0];
    const int*   n_exp  = (const int*)  d_in[1];
    const float* cls_w1 = (const float*)d_in[2];
    const float* cls_b1 = (const float*)d_in[3];
    const float* cls_w2 = (const float*)d_in[4];
    const float* cls_b2 = (const float*)d_in[5];
    const float* we_w1  = (const float*)d_in[6];
    const float* we_b1  = (const float*)d_in[7];
    const float* we_w2  = (const float*)d_in[8];
    const float* we_b2  = (const float*)d_in[9];
    const float* ew_w1  = (const float*)d_in[10];
    const float* ew_b1  = (const float*)d_in[11];
    const float* ew_w2  = (const float*)d_in[12];
    const float* ew_b2  = (const float*)d_in[13];
    float* out = (float*)d_out;

    float* h_base;
    float* cls_lg;
    float* we_lg;
    float* ew_lg;
    cudaGetSymbolAddress((void**)&h_base, g_h);
    cudaGetSymbolAddress((void**)&cls_lg, g_cls_logits);
    cudaGetSymbolAddress((void**)&we_lg,  g_we_logits);
    cudaGetSymbolAddress((void**)&ew_lg,  g_ew_logits);

    const int BD = BATCH * DIM;
    dim3 blk(256);

    // fc1 (+gelu) for the three MLPs: N = 768
    dim3 g1(DIM / BN, BATCH / BM);
    sgemm_bias_act<<<g1, blk>>>(x, cls_w1, cls_b1, h_base + 0 * BD, DIM, 1);
    sgemm_bias_act<<<g1, blk>>>(x, we_w1,  we_b1,  h_base + 1 * BD, DIM, 1);
    sgemm_bias_act<<<g1, blk>>>(x, ew_w1,  ew_b1,  h_base + 2 * BD, DIM, 1);

    // fc2
    dim3 g2c((NEC + BN - 1) / BN, BATCH / BM);   // 744 -> 6 col blocks
    sgemm_bias_act<<<g2c, blk>>>(h_base + 0 * BD, cls_w2, cls_b2, cls_lg, NEC, 0);
    dim3 g2e((NEXP + BN - 1) / BN, BATCH / BM);  // 124 -> 1 col block
    sgemm_bias_act<<<g2e, blk>>>(h_base + 1 * BD, we_w2, we_b2, we_lg, NEXP, 0);
    sgemm_bias_act<<<g2e, blk>>>(h_base + 2 * BD, ew_w2, ew_b2, ew_lg, NEXP, 0);

    // per-row epilogue
    epilogue_kernel<<<BATCH, 128>>>(we_lg, ew_lg, cls_lg, n_exp, out);
}

// round 4
// speedup vs baseline: 2.5391x; 2.5391x over previous
#include <cuda_runtime.h>
#include <cuda_bf16.h>
#include <math.h>
#include <stdint.h>

#define BATCH 16384
#define DIM   768
#define NEXP  124
#define NCLS  6
#define NEC   (NEXP * NCLS)   // 744
#define NECP  768             // padded N for cls fc2
#define NEXPP 128             // padded N for we/ew fc2

// ---------------------------------------------------------------------------
// Scratch (static device globals; allocation-free at runtime)
// ---------------------------------------------------------------------------
__device__ __nv_bfloat16 g_xh[BATCH * DIM];
__device__ __nv_bfloat16 g_xl[BATCH * DIM];
__device__ __nv_bfloat16 g_hh[3][BATCH * DIM];
__device__ __nv_bfloat16 g_hl[3][BATCH * DIM];
__device__ __nv_bfloat16 g_w1h[3][DIM * DIM];
__device__ __nv_bfloat16 g_w1l[3][DIM * DIM];
__device__ __nv_bfloat16 g_w2ch[NECP * DIM];
__device__ __nv_bfloat16 g_w2cl[NECP * DIM];
__device__ __nv_bfloat16 g_w2eh[2][NEXPP * DIM];
__device__ __nv_bfloat16 g_w2el[2][NEXPP * DIM];
__device__ float g_cls_logits[BATCH * NEC];
__device__ float g_we_logits[BATCH * NEXP];
__device__ float g_ew_logits[BATCH * NEXP];

// ---------------------------------------------------------------------------
// Portable (sm_80+) PTX helpers: cp.async, ldmatrix, mma.sync bf16
// ---------------------------------------------------------------------------
__device__ __forceinline__ uint32_t smem_u32(const void* p) {
    uint32_t a;
    asm("{ .reg .u64 t; cvta.to.shared.u64 t, %1; cvt.u32.u64 %0, t; }"
        : "=r"(a) : "l"(p));
    return a;
}

__device__ __forceinline__ void cp_async16(uint32_t dst, const void* src) {
    asm volatile("cp.async.cg.shared.global [%0], [%1], 16;"
                 :: "r"(dst), "l"(src) : "memory");
}
__device__ __forceinline__ void cp_commit() {
    asm volatile("cp.async.commit_group;" ::: "memory");
}
__device__ __forceinline__ void cp_wait_all() {
    asm volatile("cp.async.wait_group 0;" ::: "memory");
}

__device__ __forceinline__ void ldsm4(uint32_t* r, uint32_t addr) {
    asm volatile("ldmatrix.sync.aligned.m8n8.x4.shared.b16 {%0,%1,%2,%3}, [%4];"
                 : "=r"(r[0]), "=r"(r[1]), "=r"(r[2]), "=r"(r[3]) : "r"(addr));
}

__device__ __forceinline__ void mma_bf16(float* c, const uint32_t* a,
                                         uint32_t b0, uint32_t b1) {
    asm volatile(
        "mma.sync.aligned.m16n8k16.row.col.f32.bf16.bf16.f32 "
        "{%0,%1,%2,%3}, {%4,%5,%6,%7}, {%8,%9}, {%0,%1,%2,%3};"
        : "+f"(c[0]), "+f"(c[1]), "+f"(c[2]), "+f"(c[3])
        : "r"(a[0]), "r"(a[1]), "r"(a[2]), "r"(a[3]), "r"(b0), "r"(b1));
}

__device__ __forceinline__ float gelu_exact(float x) {
    return 0.5f * x * (1.0f + erff(x * 0.70710678118654752f));
}

// ---------------------------------------------------------------------------
// Conversions
// ---------------------------------------------------------------------------
__global__ __launch_bounds__(256)
void convert_x_k(const float* __restrict__ x,
                 __nv_bfloat16* __restrict__ xh, __nv_bfloat16* __restrict__ xl) {
    int i = blockIdx.x * blockDim.x + threadIdx.x;   // float4 index
    float4 v = ((const float4*)x)[i];
    float a[4] = {v.x, v.y, v.z, v.w};
#pragma unroll
    for (int c = 0; c < 4; c++) {
        __nv_bfloat16 h = __float2bfloat16(a[c]);
        xh[4 * i + c] = h;
        xl[4 * i + c] = __float2bfloat16(a[c] - __bfloat162float(h));
    }
}

// W[K=768][Nsrc] fp32 -> Th/Tl[Npad][768] bf16 (transposed, padded rows zero)
__global__ __launch_bounds__(256)
void wconv_k(const float* __restrict__ W, int Nsrc,
             __nv_bfloat16* __restrict__ Th, __nv_bfloat16* __restrict__ Tl) {
    __shared__ float tile[32][33];
    int n0 = blockIdx.x * 32, k0 = blockIdx.y * 32;
    int tx = threadIdx.x, ty = threadIdx.y;
    for (int i = ty; i < 32; i += 8) {
        int n = n0 + tx;
        tile[i][tx] = (n < Nsrc) ? W[(size_t)(k0 + i) * Nsrc + n] : 0.0f;
    }
    __syncthreads();
    for (int i = ty; i < 32; i += 8) {
        float v = tile[tx][i];     // = W[k0+tx][n0+i]
        __nv_bfloat16 h = __float2bfloat16(v);
        size_t o = (size_t)(n0 + i) * DIM + (k0 + tx);
        Th[o] = h;
        Tl[o] = __float2bfloat16(v - __bfloat162float(h));
    }
}

// ---------------------------------------------------------------------------
// Split-bf16 GEMM via mma.sync (HMMA):
//   D[128,128] tile of A[M,768] @ W[768,N], A/W as bf16 hi+lo, fp32 accum.
//   A: [M,768] K-major; B: [Npad,768] (transposed weights) K-major.
// mode 0: outF = D + bias (guard col < Nreal)
// mode 1: g = gelu(D + bias); outH/outL = split-bf16(g)  (N = 768)
// ---------------------------------------------------------------------------
#define BK 64
#define NSTAGE (DIM / BK)            // 12
#define TILE_B 16384                 // one 128x64 bf16 tile
#define BUF_BYTES (4 * TILE_B)       // Ah, Al, Bh, Bl
#define SMEM_TOTAL (2 * BUF_BYTES)   // 131072

__global__ __launch_bounds__(256, 1)
void gemm_mma_split(const __nv_bfloat16* __restrict__ Ah,
                    const __nv_bfloat16* __restrict__ Al,
                    const __nv_bfloat16* __restrict__ Bh,
                    const __nv_bfloat16* __restrict__ Bl,
                    const float* __restrict__ bias,
                    float* __restrict__ outF,
                    __nv_bfloat16* __restrict__ outH,
                    __nv_bfloat16* __restrict__ outL,
                    int Nreal, int mode)
{
    extern __shared__ __align__(1024) char dyn[];
    const int tid  = threadIdx.x;
    const int lane = tid & 31;
    const int wid  = tid >> 5;
    const int m0 = blockIdx.y * 128;
    const int n0 = blockIdx.x * 128;
    const uint32_t smem = smem_u32(dyn);

    // warp tile: 32 (m) x 64 (n); warps arranged 4 (m) x 2 (n)
    const int wm = (wid >> 1) * 32;
    const int wn = (wid & 1) * 64;

    // ldmatrix lane-derived indices
    const int lr = lane & 7;
    const int aRowBase = wm + lr + 8 * ((lane >> 3) & 1);   // + 16*i
    const int aChunkSel = lane >> 4;                        // 0/1
    const int bRowBase = wn + lr + 8 * (lane >> 4);         // + 16*jj
    const int bChunkSel = (lane >> 3) & 1;                  // 0/1

    float acc[2][8][4];
#pragma unroll
    for (int i = 0; i < 2; i++)
#pragma unroll
        for (int j = 0; j < 8; j++)
#pragma unroll
            for (int r = 0; r < 4; r++) acc[i][j][r] = 0.0f;

    // ---- stage loader (global -> swizzled SMEM via cp.async) ----
    auto load_stage = [&](int s, int p) {
        const int k0 = s * BK;
        const uint32_t sb = smem + p * BUF_BYTES;
#pragma unroll
        for (int it = 0; it < 4; ++it) {
            int idx = it * 256 + tid;     // 0..1023
            int row = idx >> 3;           // 0..127
            int ch  = idx & 7;            // 16B chunk
            uint32_t sw = (uint32_t)(row * 128 + ((ch ^ (row & 7)) << 4));
            size_t aoff = (size_t)(m0 + row) * DIM + k0 + ch * 8;
            size_t boff = (size_t)(n0 + row) * DIM + k0 + ch * 8;
            cp_async16(sb + 0 * TILE_B + sw, Ah + aoff);
            cp_async16(sb + 1 * TILE_B + sw, Al + aoff);
            cp_async16(sb + 2 * TILE_B + sw, Bh + boff);
            cp_async16(sb + 3 * TILE_B + sw, Bl + boff);
        }
        cp_commit();
    };

    load_stage(0, 0);

#pragma unroll 1
    for (int s = 0; s < NSTAGE; ++s) {
        const int p = s & 1;
        cp_wait_all();
        __syncthreads();
        if (s + 1 < NSTAGE) load_stage(s + 1, p ^ 1);

        const uint32_t base = smem + p * BUF_BYTES;
#pragma unroll
        for (int kk = 0; kk < 4; ++kk) {
            uint32_t ah[2][4], al[2][4];
#pragma unroll
            for (int i = 0; i < 2; ++i) {
                int r = aRowBase + 16 * i;
                uint32_t addr = base + (uint32_t)(r * 128)
                              + (uint32_t)((((2 * kk + aChunkSel) ^ (r & 7)) << 4));
                ldsm4(ah[i], addr);
                ldsm4(al[i], addr + TILE_B);
            }
            uint32_t bh[4][4], bl[4][4];
#pragma unroll
            for (int jj = 0; jj < 4; ++jj) {
                int r = bRowBase + 16 * jj;
                uint32_t addr = base + 2 * TILE_B + (uint32_t)(r * 128)
                              + (uint32_t)((((2 * kk + bChunkSel) ^ (r & 7)) << 4));
                ldsm4(bh[jj], addr);
                ldsm4(bl[jj], addr + TILE_B);
            }
#pragma unroll
            for (int i = 0; i < 2; ++i)
#pragma unroll
                for (int j = 0; j < 8; ++j) {
                    const uint32_t* bhf = &bh[j >> 1][(j & 1) * 2];
                    const uint32_t* blf = &bl[j >> 1][(j & 1) * 2];
                    mma_bf16(acc[i][j], ah[i], bhf[0], bhf[1]);
                    mma_bf16(acc[i][j], ah[i], blf[0], blf[1]);
                    mma_bf16(acc[i][j], al[i], bhf[0], bhf[1]);
                }
        }
    }

    // ---- epilogue from registers ----
    const int qrow = lane >> 2;          // 0..7
    const int qcol = (lane & 3) * 2;     // 0,2,4,6
#pragma unroll
    for (int i = 0; i < 2; ++i) {
        int r0 = m0 + wm + 16 * i + qrow;
        int r1 = r0 + 8;
#pragma unroll
        for (int j = 0; j < 8; ++j) {
            int col = n0 + wn + j * 8 + qcol;
            if (mode == 1) {
                float2 bv = *(const float2*)(bias + col);
                float g0 = gelu_exact(acc[i][j][0] + bv.x);
                float g1 = gelu_exact(acc[i][j][1] + bv.y);
                float g2 = gelu_exact(acc[i][j][2] + bv.x);
                float g3 = gelu_exact(acc[i][j][3] + bv.y);
                __nv_bfloat162 h01, h23, l01, l23;
                h01.x = __float2bfloat16(g0); h01.y = __float2bfloat16(g1);
                h23.x = __float2bfloat16(g2); h23.y = __float2bfloat16(g3);
                l01.x = __float2bfloat16(g0 - __bfloat162float(h01.x));
                l01.y = __float2bfloat16(g1 - __bfloat162float(h01.y));
                l23.x = __float2bfloat16(g2 - __bfloat162float(h23.x));
                l23.y = __float2bfloat16(g3 - __bfloat162float(h23.y));
                *(__nv_bfloat162*)(outH + (size_t)r0 * DIM + col) = h01;
                *(__nv_bfloat162*)(outH + (size_t)r1 * DIM + col) = h23;
                *(__nv_bfloat162*)(outL + (size_t)r0 * DIM + col) = l01;
                *(__nv_bfloat162*)(outL + (size_t)r1 * DIM + col) = l23;
            } else {
                if (col < Nreal) {
                    float2 bv = *(const float2*)(bias + col);
                    float2 o0, o1;
                    o0.x = acc[i][j][0] + bv.x; o0.y = acc[i][j][1] + bv.y;
                    o1.x = acc[i][j][2] + bv.x; o1.y = acc[i][j][3] + bv.y;
                    *(float2*)(outF + (size_t)r0 * Nreal + col) = o0;
                    *(float2*)(outF + (size_t)r1 * Nreal + col) = o1;
                }
            }
        }
    }
}

// ---------------------------------------------------------------------------
// Row-wise epilogue (unchanged, verified at rel_err 9.4e-8)
// ---------------------------------------------------------------------------
__global__ __launch_bounds__(128)
void epilogue_kernel(const float* __restrict__ we_l,
                     const float* __restrict__ ew_l,
                     const float* __restrict__ cls_l,
                     const int*   __restrict__ n_experts,
                     float* __restrict__ out)
{
    const int row  = blockIdx.x;
    const int t    = threadIdx.x;
    const int lane = t & 31;
    const int warp = t >> 5;

    __shared__ float s_we[128];
    __shared__ float s_thr;
    __shared__ float s_red[4];
    __shared__ float s_part[4][NCLS];

    const float NEG_INF = -__int_as_float(0x7f800000);

    float v = (t < NEXP) ? we_l[row * NEXP + t] : NEG_INF;
    s_we[t] = v;
    __syncthreads();

    int n = n_experts[row];
    n = (n < NEXP) ? n : NEXP;

    if (t < NEXP) {
        int cgt = 0, ceq = 0;
#pragma unroll 4
        for (int j = 0; j < NEXP; j++) {
            float u = s_we[j];
            cgt += (u > v);
            ceq += (u == v);
        }
        if (cgt <= n - 1 && cgt + ceq > n - 1) s_thr = v;
    }
    __syncthreads();
    float thr = s_thr;

    float ewv = NEG_INF;
    if (t < NEXP && v >= thr) ewv = ew_l[row * NEXP + t];

    float m = ewv;
#pragma unroll
    for (int o = 16; o > 0; o >>= 1) m = fmaxf(m, __shfl_xor_sync(0xffffffffu, m, o));
    if (lane == 0) s_red[warp] = m;
    __syncthreads();
    m = fmaxf(fmaxf(s_red[0], s_red[1]), fmaxf(s_red[2], s_red[3]));
    __syncthreads();

    float e = expf(ewv - m);

    float se = e;
#pragma unroll
    for (int o = 16; o > 0; o >>= 1) se += __shfl_xor_sync(0xffffffffu, se, o);
    if (lane == 0) s_red[warp] = se;
    __syncthreads();
    se = s_red[0] + s_red[1] + s_red[2] + s_red[3];

    float part[NCLS];
#pragma unroll
    for (int c = 0; c < NCLS; c++) part[c] = 0.0f;
    if (t < NEXP) {
        float l[NCLS];
#pragma unroll
        for (int c = 0; c < NCLS; c++) l[c] = cls_l[row * NEC + t * NCLS + c];
        float mx = l[0];
#pragma unroll
        for (int c = 1; c < NCLS; c++) mx = fmaxf(mx, l[c]);
        float s = 0.0f;
#pragma unroll
        for (int c = 0; c < NCLS; c++) { l[c] = expf(l[c] - mx); s += l[c]; }
        float scale = e / s;
#pragma unroll
        for (int c = 0; c < NCLS; c++) part[c] = l[c] * scale;
    }

#pragma unroll
    for (int c = 0; c < NCLS; c++) {
        float p = part[c];
#pragma unroll
        for (int o = 16; o > 0; o >>= 1) p += __shfl_xor_sync(0xffffffffu, p, o);
        part[c] = p;
    }
    if (lane == 0)
#pragma unroll
        for (int c = 0; c < NCLS; c++) s_part[warp][c] = part[c];
    __syncthreads();

    if (t < NCLS) {
        float tot = s_part[0][t] + s_part[1][t] + s_part[2][t] + s_part[3][t];
        out[row * NCLS + t] = tot / se;
    }
}

// ---------------------------------------------------------------------------
// Launch
// ---------------------------------------------------------------------------
extern "C" void kernel_launch(void* const* d_in, const int* in_sizes, int n_in,
                              void* d_out, int out_size)
{
    const float* x      = (const float*)d_in[0];
    const int*   n_exp  = (const int*)  d_in[1];
    const float* cls_w1 = (const float*)d_in[2];
    const float* cls_b1 = (const float*)d_in[3];
    const float* cls_w2 = (const float*)d_in[4];
    const float* cls_b2 = (const float*)d_in[5];
    const float* we_w1  = (const float*)d_in[6];
    const float* we_b1  = (const float*)d_in[7];
    const float* we_w2  = (const float*)d_in[8];
    const float* we_b2  = (const float*)d_in[9];
    const float* ew_w1  = (const float*)d_in[10];
    const float* ew_b1  = (const float*)d_in[11];
    const float* ew_w2  = (const float*)d_in[12];
    const float* ew_b2  = (const float*)d_in[13];
    float* out = (float*)d_out;

    __nv_bfloat16 *xh, *xl, *hh, *hl, *w1h, *w1l, *w2ch, *w2cl, *w2eh, *w2el;
    float *cls_lg, *we_lg, *ew_lg;
    cudaGetSymbolAddress((void**)&xh,   g_xh);
    cudaGetSymbolAddress((void**)&xl,   g_xl);
    cudaGetSymbolAddress((void**)&hh,   g_hh);
    cudaGetSymbolAddress((void**)&hl,   g_hl);
    cudaGetSymbolAddress((void**)&w1h,  g_w1h);
    cudaGetSymbolAddress((void**)&w1l,  g_w1l);
    cudaGetSymbolAddress((void**)&w2ch, g_w2ch);
    cudaGetSymbolAddress((void**)&w2cl, g_w2cl);
    cudaGetSymbolAddress((void**)&w2eh, g_w2eh);
    cudaGetSymbolAddress((void**)&w2el, g_w2el);
    cudaGetSymbolAddress((void**)&cls_lg, g_cls_logits);
    cudaGetSymbolAddress((void**)&we_lg,  g_we_logits);
    cudaGetSymbolAddress((void**)&ew_lg,  g_ew_logits);

    cudaFuncSetAttribute(gemm_mma_split,
                         cudaFuncAttributeMaxDynamicSharedMemorySize, SMEM_TOTAL);

    const size_t BD = (size_t)BATCH * DIM;
    const size_t WD = (size_t)DIM * DIM;
    const size_t ED = (size_t)NEXPP * DIM;

    // 1) convert inputs/weights to split-bf16
    convert_x_k<<<(BATCH * DIM) / 1024, 256>>>(x, xh, xl);
    dim3 tb(32, 8);
    wconv_k<<<dim3(DIM / 32, DIM / 32), tb>>>(cls_w1, DIM, w1h + 0 * WD, w1l + 0 * WD);
    wconv_k<<<dim3(DIM / 32, DIM / 32), tb>>>(we_w1,  DIM, w1h + 1 * WD, w1l + 1 * WD);
    wconv_k<<<dim3(DIM / 32, DIM / 32), tb>>>(ew_w1,  DIM, w1h + 2 * WD, w1l + 2 * WD);
    wconv_k<<<dim3(NECP / 32, DIM / 32), tb>>>(cls_w2, NEC, w2ch, w2cl);
    wconv_k<<<dim3(NEXPP / 32, DIM / 32), tb>>>(we_w2, NEXP, w2eh + 0 * ED, w2el + 0 * ED);
    wconv_k<<<dim3(NEXPP / 32, DIM / 32), tb>>>(ew_w2, NEXP, w2eh + 1 * ED, w2el + 1 * ED);

    // 2) fc1 (+gelu, fused split-bf16 output)
    dim3 blk(256);
    dim3 g1(DIM / 128, BATCH / 128);
    gemm_mma_split<<<g1, blk, SMEM_TOTAL>>>(xh, xl, w1h + 0 * WD, w1l + 0 * WD, cls_b1,
                                            nullptr, hh + 0 * BD, hl + 0 * BD, DIM, 1);
    gemm_mma_split<<<g1, blk, SMEM_TOTAL>>>(xh, xl, w1h + 1 * WD, w1l + 1 * WD, we_b1,
                                            nullptr, hh + 1 * BD, hl + 1 * BD, DIM, 1);
    gemm_mma_split<<<g1, blk, SMEM_TOTAL>>>(xh, xl, w1h + 2 * WD, w1l + 2 * WD, ew_b1,
                                            nullptr, hh + 2 * BD, hl + 2 * BD, DIM, 1);

    // 3) fc2 -> fp32 logits
    dim3 g2c(NECP / 128, BATCH / 128);
    gemm_mma_split<<<g2c, blk, SMEM_TOTAL>>>(hh + 0 * BD, hl + 0 * BD, w2ch, w2cl, cls_b2,
                                             cls_lg, nullptr, nullptr, NEC, 0);
    dim3 g2e(NEXPP / 128, BATCH / 128);
    gemm_mma_split<<<g2e, blk, SMEM_TOTAL>>>(hh + 1 * BD, hl + 1 * BD,
                                             w2eh + 0 * ED, w2el + 0 * ED, we_b2,
                                             we_lg, nullptr, nullptr, NEXP, 0);
    gemm_mma_split<<<g2e, blk, SMEM_TOTAL>>>(hh + 2 * BD, hl + 2 * BD,
                                             w2eh + 1 * ED, w2el + 1 * ED, ew_b2,
                                             ew_lg, nullptr, nullptr, NEXP, 0);

    // 4) row-wise softmax/topk epilogue
    epilogue_kernel<<<BATCH, 128>>>(we_lg, ew_lg, cls_lg, n_exp, out);
}

// round 5
// speedup vs baseline: 2.7619x; 1.0878x over previous
#include <cuda_runtime.h>
#include <cuda_bf16.h>
#include <math.h>
#include <stdint.h>

#define BATCH 16384
#define DIM   768
#define NEXP  124
#define NCLS  6
#define NEC   (NEXP * NCLS)   // 744
#define NECP  768             // padded N for cls fc2
#define NEXPP 128             // padded N for we/ew fc2

// ---------------------------------------------------------------------------
// Scratch (static device globals; allocation-free at runtime)
// ---------------------------------------------------------------------------
__device__ __nv_bfloat16 g_xh[BATCH * DIM];
__device__ __nv_bfloat16 g_xl[BATCH * DIM];
__device__ __nv_bfloat16 g_hh[3][BATCH * DIM];
__device__ __nv_bfloat16 g_hl[3][BATCH * DIM];
__device__ __nv_bfloat16 g_w1h[3][DIM * DIM];
__device__ __nv_bfloat16 g_w1l[3][DIM * DIM];
__device__ __nv_bfloat16 g_w2ch[NECP * DIM];
__device__ __nv_bfloat16 g_w2cl[NECP * DIM];
__device__ __nv_bfloat16 g_w2eh[2][NEXPP * DIM];
__device__ __nv_bfloat16 g_w2el[2][NEXPP * DIM];
__device__ float g_cls_logits[BATCH * NEC];
__device__ float g_we_logits[BATCH * NEXP];
__device__ float g_ew_logits[BATCH * NEXP];

// ---------------------------------------------------------------------------
// Portable (sm_80+) PTX helpers
// ---------------------------------------------------------------------------
__device__ __forceinline__ uint32_t smem_u32(const void* p) {
    uint32_t a;
    asm("{ .reg .u64 t; cvta.to.shared.u64 t, %1; cvt.u32.u64 %0, t; }"
        : "=r"(a) : "l"(p));
    return a;
}

__device__ __forceinline__ void cp_async16(uint32_t dst, const void* src) {
    asm volatile("cp.async.cg.shared.global [%0], [%1], 16;"
                 :: "r"(dst), "l"(src) : "memory");
}
__device__ __forceinline__ void cp_commit() {
    asm volatile("cp.async.commit_group;" ::: "memory");
}
__device__ __forceinline__ void cp_wait1() {
    asm volatile("cp.async.wait_group 1;" ::: "memory");
}

__device__ __forceinline__ void ldsm4(uint32_t* r, uint32_t addr) {
    asm volatile("ldmatrix.sync.aligned.m8n8.x4.shared.b16 {%0,%1,%2,%3}, [%4];"
                 : "=r"(r[0]), "=r"(r[1]), "=r"(r[2]), "=r"(r[3]) : "r"(addr));
}

__device__ __forceinline__ void mma_bf16(float* c, const uint32_t* a,
                                         uint32_t b0, uint32_t b1) {
    asm volatile(
        "mma.sync.aligned.m16n8k16.row.col.f32.bf16.bf16.f32 "
        "{%0,%1,%2,%3}, {%4,%5,%6,%7}, {%8,%9}, {%0,%1,%2,%3};"
        : "+f"(c[0]), "+f"(c[1]), "+f"(c[2]), "+f"(c[3])
        : "r"(a[0]), "r"(a[1]), "r"(a[2]), "r"(a[3]), "r"(b0), "r"(b1));
}

__device__ __forceinline__ float gelu_exact(float x) {
    return 0.5f * x * (1.0f + erff(x * 0.70710678118654752f));
}

// ---------------------------------------------------------------------------
// Conversions
// ---------------------------------------------------------------------------
__global__ __launch_bounds__(256)
void convert_x_k(const float* __restrict__ x,
                 __nv_bfloat16* __restrict__ xh, __nv_bfloat16* __restrict__ xl) {
    int i = blockIdx.x * blockDim.x + threadIdx.x;
    float4 v = ((const float4*)x)[i];
    float a[4] = {v.x, v.y, v.z, v.w};
#pragma unroll
    for (int c = 0; c < 4; c++) {
        __nv_bfloat16 h = __float2bfloat16(a[c]);
        xh[4 * i + c] = h;
        xl[4 * i + c] = __float2bfloat16(a[c] - __bfloat162float(h));
    }
}

// Merged weight conversion: z selects which weight matrix.
// W[K=768][Nsrc] fp32 -> Th/Tl[Npad][768] bf16 (transposed, padded rows zero)
__global__ __launch_bounds__(256)
void wconv_all_k(const float* __restrict__ cls_w1, const float* __restrict__ we_w1,
                 const float* __restrict__ ew_w1,  const float* __restrict__ cls_w2,
                 const float* __restrict__ we_w2,  const float* __restrict__ ew_w2)
{
    const int z = blockIdx.z;
    const float* W; int Nsrc, Npad;
    __nv_bfloat16 *Th, *Tl;
    switch (z) {
    case 0: W = cls_w1; Nsrc = DIM;  Npad = DIM;   Th = g_w1h[0]; Tl = g_w1l[0]; break;
    case 1: W = we_w1;  Nsrc = DIM;  Npad = DIM;   Th = g_w1h[1]; Tl = g_w1l[1]; break;
    case 2: W = ew_w1;  Nsrc = DIM;  Npad = DIM;   Th = g_w1h[2]; Tl = g_w1l[2]; break;
    case 3: W = cls_w2; Nsrc = NEC;  Npad = NECP;  Th = g_w2ch;   Tl = g_w2cl;   break;
    case 4: W = we_w2;  Nsrc = NEXP; Npad = NEXPP; Th = g_w2eh[0]; Tl = g_w2el[0]; break;
    default:W = ew_w2;  Nsrc = NEXP; Npad = NEXPP; Th = g_w2eh[1]; Tl = g_w2el[1]; break;
    }
    int n0 = blockIdx.x * 32, k0 = blockIdx.y * 32;
    if (n0 >= Npad) return;
    __shared__ float tile[32][33];
    int tx = threadIdx.x, ty = threadIdx.y;
    for (int i = ty; i < 32; i += 8) {
        int n = n0 + tx;
        tile[i][tx] = (n < Nsrc) ? W[(size_t)(k0 + i) * Nsrc + n] : 0.0f;
    }
    __syncthreads();
    for (int i = ty; i < 32; i += 8) {
        float v = tile[tx][i];
        __nv_bfloat16 h = __float2bfloat16(v);
        size_t o = (size_t)(n0 + i) * DIM + (k0 + tx);
        Th[o] = h;
        Tl[o] = __float2bfloat16(v - __bfloat162float(h));
    }
}

// ---------------------------------------------------------------------------
// Split-bf16 GEMM core (HMMA), 512 threads, 16 warps (4m x 4n), warp tile
// 32x32, CTA tile 128x128, BK=64, 3-stage cp.async ring, SW swizzle.
// ---------------------------------------------------------------------------
#define BK 64
#define NKSTAGE (DIM / BK)           // 12
#define TILE_B 16384                 // one 128x64 bf16 tile
#define BUF_BYTES (4 * TILE_B)       // Ah, Al, Bh, Bl  (64 KB)
#define NPIPE 3
#define SMEM_TOTAL (NPIPE * BUF_BYTES)  // 196608

struct GemmOut {
    float* outF;               // mode 0
    __nv_bfloat16* outH;       // mode 1
    __nv_bfloat16* outL;       // mode 1
    const float* bias;
    int Nreal;                 // real (unpadded) column count / row stride
    int mode;
};

__device__ __forceinline__
void gemm_core(const __nv_bfloat16* __restrict__ Ah,
               const __nv_bfloat16* __restrict__ Al,
               const __nv_bfloat16* __restrict__ Bh,
               const __nv_bfloat16* __restrict__ Bl,
               const GemmOut& o, int m0, int n0, char* dyn)
{
    const int tid  = threadIdx.x;
    const int lane = tid & 31;
    const int wid  = tid >> 5;
    const uint32_t smem = smem_u32(dyn);

    const int wm = (wid >> 2) * 32;      // 0,32,64,96
    const int wn = (wid & 3) * 32;       // 0,32,64,96

    const int lr = lane & 7;
    const int aRowBase = wm + lr + 8 * ((lane >> 3) & 1);   // + 16*i
    const int aChunkSel = lane >> 4;
    const int bRowBase = wn + lr + 8 * (lane >> 4);         // + 16*jj
    const int bChunkSel = (lane >> 3) & 1;

    float acc[2][4][4];
#pragma unroll
    for (int i = 0; i < 2; i++)
#pragma unroll
        for (int j = 0; j < 4; j++)
#pragma unroll
            for (int r = 0; r < 4; r++) acc[i][j][r] = 0.0f;

    auto load_stage = [&](int s) {
        const int k0 = s * BK;
        const uint32_t sb = smem + (s % NPIPE) * BUF_BYTES;
#pragma unroll
        for (int it = 0; it < 2; ++it) {
            int idx = it * 512 + tid;     // 0..1023
            int row = idx >> 3;           // 0..127
            int ch  = idx & 7;            // 16B chunk
            uint32_t sw = (uint32_t)(row * 128 + ((ch ^ (row & 7)) << 4));
            size_t aoff = (size_t)(m0 + row) * DIM + k0 + ch * 8;
            size_t boff = (size_t)(n0 + row) * DIM + k0 + ch * 8;
            cp_async16(sb + 0 * TILE_B + sw, Ah + aoff);
            cp_async16(sb + 1 * TILE_B + sw, Al + aoff);
            cp_async16(sb + 2 * TILE_B + sw, Bh + boff);
            cp_async16(sb + 3 * TILE_B + sw, Bl + boff);
        }
        cp_commit();
    };

    load_stage(0);
    load_stage(1);

#pragma unroll 1
    for (int s = 0; s < NKSTAGE; ++s) {
        cp_wait1();            // stage s resident
        __syncthreads();       // all warps done with buffer (s+2)%NPIPE's old data
        if (s + 2 < NKSTAGE) load_stage(s + 2); else cp_commit();

        const uint32_t base = smem + (s % NPIPE) * BUF_BYTES;
#pragma unroll
        for (int kk = 0; kk < 4; ++kk) {
            uint32_t ah[2][4], al[2][4], bh[2][4], bl[2][4];
#pragma unroll
            for (int i = 0; i < 2; ++i) {
                int r = aRowBase + 16 * i;
                uint32_t addr = base + (uint32_t)(r * 128)
                              + (uint32_t)((((2 * kk + aChunkSel) ^ (r & 7)) << 4));
                ldsm4(ah[i], addr);
                ldsm4(al[i], addr + TILE_B);
            }
#pragma unroll
            for (int jj = 0; jj < 2; ++jj) {
                int r = bRowBase + 16 * jj;
                uint32_t addr = base + 2 * TILE_B + (uint32_t)(r * 128)
                              + (uint32_t)((((2 * kk + bChunkSel) ^ (r & 7)) << 4));
                ldsm4(bh[jj], addr);
                ldsm4(bl[jj], addr + TILE_B);
            }
            // term-outer ordering: same-acc reuse distance = 8 MMAs
#pragma unroll
            for (int i = 0; i < 2; ++i)
#pragma unroll
                for (int j = 0; j < 4; ++j)
                    mma_bf16(acc[i][j], ah[i],
                             bh[j >> 1][(j & 1) * 2], bh[j >> 1][(j & 1) * 2 + 1]);
#pragma unroll
            for (int i = 0; i < 2; ++i)
#pragma unroll
                for (int j = 0; j < 4; ++j)
                    mma_bf16(acc[i][j], ah[i],
                             bl[j >> 1][(j & 1) * 2], bl[j >> 1][(j & 1) * 2 + 1]);
#pragma unroll
            for (int i = 0; i < 2; ++i)
#pragma unroll
                for (int j = 0; j < 4; ++j)
                    mma_bf16(acc[i][j], al[i],
                             bh[j >> 1][(j & 1) * 2], bh[j >> 1][(j & 1) * 2 + 1]);
        }
    }

    // ---- epilogue from registers ----
    const int qrow = lane >> 2;
    const int qcol = (lane & 3) * 2;
#pragma unroll
    for (int i = 0; i < 2; ++i) {
        int r0 = m0 + wm + 16 * i + qrow;
        int r1 = r0 + 8;
#pragma unroll
        for (int j = 0; j < 4; ++j) {
            int col = n0 + wn + j * 8 + qcol;
            if (o.mode == 1) {
                float2 bv = *(const float2*)(o.bias + col);
                float g0 = gelu_exact(acc[i][j][0] + bv.x);
                float g1 = gelu_exact(acc[i][j][1] + bv.y);
                float g2 = gelu_exact(acc[i][j][2] + bv.x);
                float g3 = gelu_exact(acc[i][j][3] + bv.y);
                __nv_bfloat162 h01, h23, l01, l23;
                h01.x = __float2bfloat16(g0); h01.y = __float2bfloat16(g1);
                h23.x = __float2bfloat16(g2); h23.y = __float2bfloat16(g3);
                l01.x = __float2bfloat16(g0 - __bfloat162float(h01.x));
                l01.y = __float2bfloat16(g1 - __bfloat162float(h01.y));
                l23.x = __float2bfloat16(g2 - __bfloat162float(h23.x));
                l23.y = __float2bfloat16(g3 - __bfloat162float(h23.y));
                *(__nv_bfloat162*)(o.outH + (size_t)r0 * DIM + col) = h01;
                *(__nv_bfloat162*)(o.outH + (size_t)r1 * DIM + col) = h23;
                *(__nv_bfloat162*)(o.outL + (size_t)r0 * DIM + col) = l01;
                *(__nv_bfloat162*)(o.outL + (size_t)r1 * DIM + col) = l23;
            } else {
                if (col < o.Nreal) {
                    float2 bv = *(const float2*)(o.bias + col);
                    float2 o0, o1;
                    o0.x = acc[i][j][0] + bv.x; o0.y = acc[i][j][1] + bv.y;
                    o1.x = acc[i][j][2] + bv.x; o1.y = acc[i][j][3] + bv.y;
                    *(float2*)(o.outF + (size_t)r0 * o.Nreal + col) = o0;
                    *(float2*)(o.outF + (size_t)r1 * o.Nreal + col) = o1;
                }
            }
        }
    }
}

// ---- merged fc1: grid (18, 128); layer = bx/6, n0 = (bx%6)*128 ----
__global__ __launch_bounds__(512, 1)
void fc1_merged(const float* __restrict__ b_cls, const float* __restrict__ b_we,
                const float* __restrict__ b_ew)
{
    extern __shared__ __align__(1024) char dyn[];
    const int bx = blockIdx.x;
    const int layer = bx / 6;
    const int n0 = (bx % 6) * 128;
    const int m0 = blockIdx.y * 128;
    GemmOut o;
    o.outF = nullptr;
    o.outH = g_hh[layer];
    o.outL = g_hl[layer];
    o.bias = (layer == 0) ? b_cls : (layer == 1) ? b_we : b_ew;
    o.Nreal = DIM;
    o.mode = 1;
    gemm_core(g_xh, g_xl, g_w1h[layer], g_w1l[layer], o, m0, n0, dyn);
}

// ---- merged fc2: grid (8, 128); bx<6 -> cls col block bx; 6 -> we; 7 -> ew ----
__global__ __launch_bounds__(512, 1)
void fc2_merged(const float* __restrict__ b_cls, const float* __restrict__ b_we,
                const float* __restrict__ b_ew)
{
    extern __shared__ __align__(1024) char dyn[];
    const int bx = blockIdx.x;
    const int m0 = blockIdx.y * 128;
    GemmOut o;
    o.outH = nullptr; o.outL = nullptr; o.mode = 0;
    const __nv_bfloat16 *Ah, *Al, *Bh, *Bl;
    int n0;
    if (bx < 6) {
        Ah = g_hh[0]; Al = g_hl[0]; Bh = g_w2ch; Bl = g_w2cl;
        o.outF = g_cls_logits; o.bias = b_cls; o.Nreal = NEC; n0 = bx * 128;
    } else if (bx == 6) {
        Ah = g_hh[1]; Al = g_hl[1]; Bh = g_w2eh[0]; Bl = g_w2el[0];
        o.outF = g_we_logits; o.bias = b_we; o.Nreal = NEXP; n0 = 0;
    } else {
        Ah = g_hh[2]; Al = g_hl[2]; Bh = g_w2eh[1]; Bl = g_w2el[1];
        o.outF = g_ew_logits; o.bias = b_ew; o.Nreal = NEXP; n0 = 0;
    }
    gemm_core(Ah, Al, Bh, Bl, o, m0, n0, dyn);
}

// ---------------------------------------------------------------------------
// Row-wise epilogue (unchanged, verified)
// ---------------------------------------------------------------------------
__global__ __launch_bounds__(128)
void epilogue_kernel(const float* __restrict__ we_l,
                     const float* __restrict__ ew_l,
                     const float* __restrict__ cls_l,
                     const int*   __restrict__ n_experts,
                     float* __restrict__ out)
{
    const int row  = blockIdx.x;
    const int t    = threadIdx.x;
    const int lane = t & 31;
    const int warp = t >> 5;

    __shared__ float s_we[128];
    __shared__ float s_thr;
    __shared__ float s_red[4];
    __shared__ float s_part[4][NCLS];

    const float NEG_INF = -__int_as_float(0x7f800000);

    float v = (t < NEXP) ? we_l[row * NEXP + t] : NEG_INF;
    s_we[t] = v;
    __syncthreads();

    int n = n_experts[row];
    n = (n < NEXP) ? n : NEXP;

    if (t < NEXP) {
        int cgt = 0, ceq = 0;
#pragma unroll 4
        for (int j = 0; j < NEXP; j++) {
            float u = s_we[j];
            cgt += (u > v);
            ceq += (u == v);
        }
        if (cgt <= n - 1 && cgt + ceq > n - 1) s_thr = v;
    }
    __syncthreads();
    float thr = s_thr;

    float ewv = NEG_INF;
    if (t < NEXP && v >= thr) ewv = ew_l[row * NEXP + t];

    float m = ewv;
#pragma unroll
    for (int o = 16; o > 0; o >>= 1) m = fmaxf(m, __shfl_xor_sync(0xffffffffu, m, o));
    if (lane == 0) s_red[warp] = m;
    __syncthreads();
    m = fmaxf(fmaxf(s_red[0], s_red[1]), fmaxf(s_red[2], s_red[3]));
    __syncthreads();

    float e = expf(ewv - m);

    float se = e;
#pragma unroll
    for (int o = 16; o > 0; o >>= 1) se += __shfl_xor_sync(0xffffffffu, se, o);
    if (lane == 0) s_red[warp] = se;
    __syncthreads();
    se = s_red[0] + s_red[1] + s_red[2] + s_red[3];

    float part[NCLS];
#pragma unroll
    for (int c = 0; c < NCLS; c++) part[c] = 0.0f;
    if (t < NEXP) {
        float l[NCLS];
#pragma unroll
        for (int c = 0; c < NCLS; c++) l[c] = cls_l[row * NEC + t * NCLS + c];
        float mx = l[0];
#pragma unroll
        for (int c = 1; c < NCLS; c++) mx = fmaxf(mx, l[c]);
        float s = 0.0f;
#pragma unroll
        for (int c = 0; c < NCLS; c++) { l[c] = expf(l[c] - mx); s += l[c]; }
        float scale = e / s;
#pragma unroll
        for (int c = 0; c < NCLS; c++) part[c] = l[c] * scale;
    }

#pragma unroll
    for (int c = 0; c < NCLS; c++) {
        float p = part[c];
#pragma unroll
        for (int o = 16; o > 0; o >>= 1) p += __shfl_xor_sync(0xffffffffu, p, o);
        part[c] = p;
    }
    if (lane == 0)
#pragma unroll
        for (int c = 0; c < NCLS; c++) s_part[warp][c] = part[c];
    __syncthreads();

    if (t < NCLS) {
        float tot = s_part[0][t] + s_part[1][t] + s_part[2][t] + s_part[3][t];
        out[row * NCLS + t] = tot / se;
    }
}

// ---------------------------------------------------------------------------
// Launch
// ---------------------------------------------------------------------------
extern "C" void kernel_launch(void* const* d_in, const int* in_sizes, int n_in,
                              void* d_out, int out_size)
{
    const float* x      = (const float*)d_in[0];
    const int*   n_exp  = (const int*)  d_in[1];
    const float* cls_w1 = (const float*)d_in[2];
    const float* cls_b1 = (const float*)d_in[3];
    const float* cls_w2 = (const float*)d_in[4];
    const float* cls_b2 = (const float*)d_in[5];
    const float* we_w1  = (const float*)d_in[6];
    const float* we_b1  = (const float*)d_in[7];
    const float* we_w2  = (const float*)d_in[8];
    const float* we_b2  = (const float*)d_in[9];
    const float* ew_w1  = (const float*)d_in[10];
    const float* ew_b1  = (const float*)d_in[11];
    const float* ew_w2  = (const float*)d_in[12];
    const float* ew_b2  = (const float*)d_in[13];
    float* out = (float*)d_out;

    __nv_bfloat16 *xh, *xl;
    float *cls_lg, *we_lg, *ew_lg;
    cudaGetSymbolAddress((void**)&xh, g_xh);
    cudaGetSymbolAddress((void**)&xl, g_xl);
    cudaGetSymbolAddress((void**)&cls_lg, g_cls_logits);
    cudaGetSymbolAddress((void**)&we_lg,  g_we_logits);
    cudaGetSymbolAddress((void**)&ew_lg,  g_ew_logits);

    cudaFuncSetAttribute(fc1_merged,
                         cudaFuncAttributeMaxDynamicSharedMemorySize, SMEM_TOTAL);
    cudaFuncSetAttribute(fc2_merged,
                         cudaFuncAttributeMaxDynamicSharedMemorySize, SMEM_TOTAL);

    // 1) conversions (2 launches)
    convert_x_k<<<(BATCH * DIM) / 1024, 256>>>(x, xh, xl);
    dim3 tb(32, 8);
    wconv_all_k<<<dim3(DIM / 32, DIM / 32, 6), tb>>>(cls_w1, we_w1, ew_w1,
                                                     cls_w2, we_w2, ew_w2);

    // 2) fc1 merged (+gelu, split-bf16 output)
    fc1_merged<<<dim3(18, BATCH / 128), 512, SMEM_TOTAL>>>(cls_b1, we_b1, ew_b1);

    // 3) fc2 merged -> fp32 logits
    fc2_merged<<<dim3(8, BATCH / 128), 512, SMEM_TOTAL>>>(cls_b2, we_b2, ew_b2);

    // 4) row-wise softmax/topk epilogue
    epilogue_kernel<<<BATCH, 128>>>(we_lg, ew_lg, cls_lg, n_exp, out);
}